// round 1
// baseline (speedup 1.0000x reference)
#include <cuda_runtime.h>
#include <cuda_bf16.h>
#include <cstdint>

#define NUM_TAGS 32
#define START_TAG 30
#define STOP_TAG 31
#define MAX_B 1024
#define SEQ_S 512

__device__ float g_partial[MAX_B];

// One warp per batch element. Lane j owns tag j.
// Linear-space forward algorithm with exponent-based renormalization.
__global__ __launch_bounds__(128) void crf_forward_kernel(
    const float* __restrict__ feats,       // [B, S, 32]
    const int*   __restrict__ labels,      // [B, S]
    const int*   __restrict__ lengths,     // [B]
    const float* __restrict__ transitions, // [32, 32]
    int B)
{
    __shared__ float sT[NUM_TAGS * NUM_TAGS];      // log transitions
    __shared__ float sAlpha[4][2][NUM_TAGS];       // per-warp double buffer

    const int tid  = threadIdx.x;
    const int w    = tid >> 5;
    const int lane = tid & 31;

    // Block-cooperative load of transitions into smem
    #pragma unroll
    for (int k = 0; k < 8; k++) {
        sT[tid + k * 128] = transitions[tid + k * 128];
    }
    __syncthreads();

    const int b = blockIdx.x * 4 + w;
    if (b >= B) return;

    // Lane j holds column j of E = exp(trans): E[i] = exp(trans[i][j])
    float Ecol[NUM_TAGS];
    #pragma unroll
    for (int i = 0; i < NUM_TAGS; i++) {
        Ecol[i] = __expf(sT[i * NUM_TAGS + lane]);
    }

    const int len = lengths[b];
    const float* fb = feats + (size_t)b * SEQ_S * NUM_TAGS;
    const int labBase = b * SEQ_S;

    // t = 0 init
    float f0 = fb[lane];
    int lab0 = labels[labBase];         // uniform load
    int lab_prev = lab0;
    float alpha = __expf(f0 + sT[START_TAG * NUM_TAGS + lane]);
    float emit = (lane == lab0) ? f0 : 0.0f;
    float pairsum = 0.0f;
    float logscale = 0.0f;

    // Software-pipelined prefetch (clamped index: always in-bounds)
    int tn = (1 < len) ? 1 : 0;
    float f_n = fb[tn * NUM_TAGS + lane];
    int lab_n = labels[labBase + tn];

    for (int t = 1; t < len; t++) {
        const float f = f_n;
        const int lab = lab_n;
        int tnext = t + 1;
        tnext = (tnext < len) ? tnext : (len - 1);
        f_n = fb[tnext * NUM_TAGS + lane];
        lab_n = labels[labBase + tnext];

        // Broadcast alpha through smem (double-buffered, 1 sync/step)
        const int p = t & 1;
        sAlpha[w][p][lane] = alpha;
        __syncwarp();
        const float4* ap = (const float4*)sAlpha[w][p];

        float acc0 = 0.0f, acc1 = 0.0f, acc2 = 0.0f, acc3 = 0.0f;
        #pragma unroll
        for (int q = 0; q < 8; q++) {
            float4 a = ap[q];
            acc0 = fmaf(a.x, Ecol[4 * q + 0], acc0);
            acc1 = fmaf(a.y, Ecol[4 * q + 1], acc1);
            acc2 = fmaf(a.z, Ecol[4 * q + 2], acc2);
            acc3 = fmaf(a.w, Ecol[4 * q + 3], acc3);
        }
        const float s = (acc0 + acc1) + (acc2 + acc3);
        const float ef = __expf(f);
        alpha = s * ef;

        // Gold score accumulation (fused)
        if (lane == lab) emit += f;
        pairsum += sT[lab_prev * NUM_TAGS + lab];  // uniform broadcast LDS
        lab_prev = lab;

        // Renormalize every 4 steps: exact power-of-two scaling
        if ((t & 3) == 0) {
            float m = alpha;
            #pragma unroll
            for (int off = 16; off >= 1; off >>= 1)
                m = fmaxf(m, __shfl_xor_sync(0xffffffffu, m, off));
            int e = (__float_as_int(m) >> 23) & 0xff;
            if (e > 0) {
                int sc = 254 - e;
                sc = (sc < 1) ? 1 : sc;
                alpha *= __int_as_float(sc << 23);
                logscale += (float)(e - 127) * 0.6931471805599453f;
            }
        }
    }

    // forward score = log(sum alpha) + logscale
    float total = alpha;
    float emit_total = emit;
    #pragma unroll
    for (int off = 16; off >= 1; off >>= 1) {
        total      += __shfl_xor_sync(0xffffffffu, total, off);
        emit_total += __shfl_xor_sync(0xffffffffu, emit_total, off);
    }
    const float fwd = __logf(total) + logscale;

    const float start_sc = sT[START_TAG * NUM_TAGS + lab0];
    const float stop_sc  = sT[lab_prev * NUM_TAGS + STOP_TAG];
    const float gold = emit_total + start_sc + pairsum + stop_sc;

    if (lane == 0) {
        g_partial[b] = fwd - gold;
    }
}

__global__ void crf_reduce_kernel(float* __restrict__ out, int B)
{
    __shared__ float red[256];
    const int tid = threadIdx.x;
    float s = 0.0f;
    for (int i = tid; i < B; i += 256) s += g_partial[i];
    red[tid] = s;
    __syncthreads();
    #pragma unroll
    for (int stride = 128; stride >= 32; stride >>= 1) {
        if (tid < stride) red[tid] += red[tid + stride];
        __syncthreads();
    }
    if (tid < 32) {
        float v = red[tid];
        #pragma unroll
        for (int off = 16; off >= 1; off >>= 1)
            v += __shfl_xor_sync(0xffffffffu, v, off);
        if (tid == 0) out[0] = v / (float)B;
    }
}

extern "C" void kernel_launch(void* const* d_in, const int* in_sizes, int n_in,
                              void* d_out, int out_size)
{
    const float* feats       = (const float*)d_in[0];
    const int*   labels      = (const int*)d_in[1];
    const int*   lengths     = (const int*)d_in[2];
    const float* transitions = (const float*)d_in[3];
    float* out = (float*)d_out;

    const int B = in_sizes[2];          // lengths has B elements
    const int blocks = (B + 3) / 4;     // 4 warps (batches) per block

    crf_forward_kernel<<<blocks, 128>>>(feats, labels, lengths, transitions, B);
    crf_reduce_kernel<<<1, 256>>>(out, B);
}

// round 2
// speedup vs baseline: 1.4720x; 1.4720x over previous
#include <cuda_runtime.h>
#include <cuda_bf16.h>
#include <cstdint>

#define NUM_TAGS 32
#define START_TAG 30
#define STOP_TAG 31
#define MAX_B 1024
#define SEQ_S 512
#define LN2F 0.6931471805599453f

__device__ float g_partial[MAX_B];

__device__ __forceinline__ unsigned long long fma2(unsigned long long a,
                                                   unsigned long long b,
                                                   unsigned long long c) {
    unsigned long long d;
    asm("fma.rn.f32x2 %0, %1, %2, %3;" : "=l"(d) : "l"(a), "l"(b), "l"(c));
    return d;
}
__device__ __forceinline__ unsigned long long add2(unsigned long long a,
                                                   unsigned long long b) {
    unsigned long long d;
    asm("add.rn.f32x2 %0, %1, %2;" : "=l"(d) : "l"(a), "l"(b));
    return d;
}
__device__ __forceinline__ void unpack2(unsigned long long v, float& lo, float& hi) {
    asm("mov.b64 {%0, %1}, %2;" : "=f"(lo), "=f"(hi) : "l"(v));
}
__device__ __forceinline__ unsigned long long pack2(float lo, float hi) {
    unsigned long long v;
    asm("mov.b64 %0, {%1, %2};" : "=l"(v) : "f"(lo), "f"(hi));
    return v;
}

// One warp per batch element; lane j owns tag j.
// Linear-space forward recursion, packed f32x2 matvec, depth-8 prefetch.
__global__ __launch_bounds__(64) void crf_forward_kernel(
    const float* __restrict__ feats,       // [B, 512, 32]
    const int*   __restrict__ labels,      // [B, 512]
    const int*   __restrict__ lengths,     // [B]
    const float* __restrict__ transitions, // [32, 32]
    int B)
{
    __shared__ float sT[NUM_TAGS * NUM_TAGS];
    __shared__ float sAlpha[2][2][NUM_TAGS];

    const int tid  = threadIdx.x;
    const int w    = tid >> 5;
    const int lane = tid & 31;

    #pragma unroll
    for (int k = 0; k < 16; k++)
        sT[tid + k * 64] = transitions[tid + k * 64];
    __syncthreads();

    const int b = blockIdx.x * 2 + w;
    if (b >= B) return;

    // Packed E columns: Epk[q] = ( exp(T[2q][lane]), exp(T[2q+1][lane]) )
    unsigned long long Epk[16];
    #pragma unroll
    for (int q = 0; q < 16; q++) {
        float e0 = __expf(sT[(2 * q) * NUM_TAGS + lane]);
        float e1 = __expf(sT[(2 * q + 1) * NUM_TAGS + lane]);
        Epk[q] = pack2(e0, e1);
    }

    const int len = lengths[b];
    const float* fb = feats + (size_t)b * SEQ_S * NUM_TAGS;
    const int labBase = b * SEQ_S;

    // Label window: lane l holds labels[base + l]; base = (t & ~31)
    int lr = labels[labBase + lane];
    const int lab0 = __shfl_sync(0xffffffffu, lr, 0);
    int lab_prev = lab0;

    const float f0 = fb[lane];
    float alpha = __expf(f0 + sT[START_TAG * NUM_TAGS + lane]);
    float emit = (lane == lab0) ? f0 : 0.0f;
    float pairsum = 0.0f;
    float logscale = 0.0f;

    // Depth-8 rolling prefetch queue for feats rows t = 1..8
    float fq[8];
    #pragma unroll
    for (int d = 0; d < 8; d++) {
        int idx = 1 + d; idx = (idx < SEQ_S) ? idx : (SEQ_S - 1);
        fq[d] = fb[idx * NUM_TAGS + lane];
    }

    int t = 1;

#define CRF_STEP(TT, FVAL, DO_PREFETCH, USLOT)                                  \
    {                                                                            \
        const int tt_ = (TT);                                                    \
        const float f_ = (FVAL);                                                 \
        if (DO_PREFETCH) {                                                       \
            int pidx = tt_ + 8; pidx = (pidx < SEQ_S) ? pidx : (SEQ_S - 1);      \
            fq[USLOT] = fb[pidx * NUM_TAGS + lane];                              \
        }                                                                        \
        if ((tt_ & 31) == 0) lr = labels[labBase + tt_ + lane];                  \
        const int lab_ = __shfl_sync(0xffffffffu, lr, tt_ & 31);                 \
        const float ef_ = __expf(f_);                                            \
        const int p_ = tt_ & 1;                                                  \
        sAlpha[w][p_][lane] = alpha;                                             \
        __syncwarp();                                                            \
        const ulonglong2* ap_ = (const ulonglong2*)sAlpha[w][p_];                \
        unsigned long long a0 = 0ull, a1 = 0ull, a2 = 0ull, a3 = 0ull;           \
        ulonglong2 v0 = ap_[0], v1 = ap_[1], v2 = ap_[2], v3 = ap_[3];           \
        a0 = fma2(v0.x, Epk[0],  a0);                                            \
        a1 = fma2(v0.y, Epk[1],  a1);                                            \
        a2 = fma2(v1.x, Epk[2],  a2);                                            \
        a3 = fma2(v1.y, Epk[3],  a3);                                            \
        a0 = fma2(v2.x, Epk[4],  a0);                                            \
        a1 = fma2(v2.y, Epk[5],  a1);                                            \
        a2 = fma2(v3.x, Epk[6],  a2);                                            \
        a3 = fma2(v3.y, Epk[7],  a3);                                            \
        ulonglong2 v4 = ap_[4], v5 = ap_[5], v6 = ap_[6], v7 = ap_[7];           \
        a0 = fma2(v4.x, Epk[8],  a0);                                            \
        a1 = fma2(v4.y, Epk[9],  a1);                                            \
        a2 = fma2(v5.x, Epk[10], a2);                                            \
        a3 = fma2(v5.y, Epk[11], a3);                                            \
        a0 = fma2(v6.x, Epk[12], a0);                                            \
        a1 = fma2(v6.y, Epk[13], a1);                                            \
        a2 = fma2(v7.x, Epk[14], a2);                                            \
        a3 = fma2(v7.y, Epk[15], a3);                                            \
        a0 = add2(a0, a1); a2 = add2(a2, a3); a0 = add2(a0, a2);                 \
        float lo_, hi_; unpack2(a0, lo_, hi_);                                   \
        alpha = (lo_ + hi_) * ef_;                                               \
        if (lane == lab_) emit += f_;                                            \
        pairsum += sT[lab_prev * NUM_TAGS + lab_];                               \
        lab_prev = lab_;                                                         \
    }

    // Main loop: 8 steps per iteration, prefetch 8 ahead, renorm once per block
    for (; t + 8 <= len; t += 8) {
        #pragma unroll
        for (int u = 0; u < 8; u++) {
            CRF_STEP(t + u, fq[u], 1, u);
        }
        // Renormalize: scale warp-max alpha to ~1.0 (exact power of two)
        unsigned mb = __reduce_max_sync(0xffffffffu, __float_as_uint(alpha));
        int e = (int)((mb >> 23) & 0xff);
        if (e > 0) {
            int sc = 254 - e; sc = (sc < 1) ? 1 : sc;
            alpha *= __int_as_float(sc << 23);
            logscale += (float)(127 - sc) * LN2F;
        }
    }

    // Tail: up to 7 remaining steps (uniform guard per warp)
    #pragma unroll
    for (int u = 0; u < 7; u++) {
        if (t + u < len) {
            CRF_STEP(t + u, fq[u], 0, u);
        }
    }

#undef CRF_STEP

    // forward score = log(sum alpha) + logscale
    float total = alpha;
    float emit_total = emit;
    #pragma unroll
    for (int off = 16; off >= 1; off >>= 1) {
        total      += __shfl_xor_sync(0xffffffffu, total, off);
        emit_total += __shfl_xor_sync(0xffffffffu, emit_total, off);
    }
    const float fwd = __logf(total) + logscale;

    const float start_sc = sT[START_TAG * NUM_TAGS + lab0];
    const float stop_sc  = sT[lab_prev * NUM_TAGS + STOP_TAG];
    const float gold = emit_total + start_sc + pairsum + stop_sc;

    if (lane == 0) g_partial[b] = fwd - gold;
}

__global__ void crf_reduce_kernel(float* __restrict__ out, int B)
{
    __shared__ float red[256];
    const int tid = threadIdx.x;
    float s = 0.0f;
    for (int i = tid; i < B; i += 256) s += g_partial[i];
    red[tid] = s;
    __syncthreads();
    #pragma unroll
    for (int stride = 128; stride >= 32; stride >>= 1) {
        if (tid < stride) red[tid] += red[tid + stride];
        __syncthreads();
    }
    if (tid < 32) {
        float v = red[tid];
        #pragma unroll
        for (int off = 16; off >= 1; off >>= 1)
            v += __shfl_xor_sync(0xffffffffu, v, off);
        if (tid == 0) out[0] = v / (float)B;
    }
}

extern "C" void kernel_launch(void* const* d_in, const int* in_sizes, int n_in,
                              void* d_out, int out_size)
{
    const float* feats       = (const float*)d_in[0];
    const int*   labels      = (const int*)d_in[1];
    const int*   lengths     = (const int*)d_in[2];
    const float* transitions = (const float*)d_in[3];
    float* out = (float*)d_out;

    const int B = in_sizes[2];
    const int blocks = (B + 1) / 2;   // 2 warps (batches) per 64-thread block

    crf_forward_kernel<<<blocks, 64>>>(feats, labels, lengths, transitions, B);
    crf_reduce_kernel<<<1, 256>>>(out, B);
}

// round 3
// speedup vs baseline: 1.9113x; 1.2984x over previous
#include <cuda_runtime.h>
#include <cuda_bf16.h>
#include <cstdint>

#define NUM_TAGS 32
#define START_TAG 30
#define STOP_TAG 31
#define MAX_B 1024
#define SEQ_S 512
#define LN2F 0.6931471805599453f

__device__ float g_partial[MAX_B];
__device__ unsigned g_done = 0;

__device__ __forceinline__ unsigned long long fma2(unsigned long long a,
                                                   unsigned long long b,
                                                   unsigned long long c) {
    unsigned long long d;
    asm("fma.rn.f32x2 %0, %1, %2, %3;" : "=l"(d) : "l"(a), "l"(b), "l"(c));
    return d;
}
__device__ __forceinline__ unsigned long long add2(unsigned long long a,
                                                   unsigned long long b) {
    unsigned long long d;
    asm("add.rn.f32x2 %0, %1, %2;" : "=l"(d) : "l"(a), "l"(b));
    return d;
}
__device__ __forceinline__ void unpack2(unsigned long long v, float& lo, float& hi) {
    asm("mov.b64 {%0, %1}, %2;" : "=f"(lo), "=f"(hi) : "l"(v));
}
__device__ __forceinline__ unsigned long long pack2(float lo, float hi) {
    unsigned long long v;
    asm("mov.b64 %0, {%1, %2};" : "=l"(v) : "f"(lo), "f"(hi));
    return v;
}

// One warp per batch; lane j owns tag j. Pure linear-space recursion in the
// hot loop; gold score computed in a latency-tolerant epilogue.
__global__ __launch_bounds__(64) void crf_forward_kernel(
    const float* __restrict__ feats,       // [B, 512, 32]
    const int*   __restrict__ labels,      // [B, 512]
    const int*   __restrict__ lengths,     // [B]
    const float* __restrict__ transitions, // [32, 32]
    float* __restrict__ out, int B, int nblocks)
{
    __shared__ float sT[NUM_TAGS * NUM_TAGS];
    __shared__ float sAlpha[2][2][NUM_TAGS];
    __shared__ float sred[64];
    __shared__ int sIsLast;

    const int tid  = threadIdx.x;
    const int w    = tid >> 5;
    const int lane = tid & 31;

    #pragma unroll
    for (int k = 0; k < 16; k++)
        sT[tid + k * 64] = transitions[tid + k * 64];
    __syncthreads();

    const int b = blockIdx.x * 2 + w;

    if (b < B) {
        // Packed E columns: Epk[q] = ( exp(T[2q][lane]), exp(T[2q+1][lane]) )
        unsigned long long Epk[16];
        #pragma unroll
        for (int q = 0; q < 16; q++) {
            float e0 = __expf(sT[(2 * q) * NUM_TAGS + lane]);
            float e1 = __expf(sT[(2 * q + 1) * NUM_TAGS + lane]);
            Epk[q] = pack2(e0, e1);
        }

        const int len = lengths[b];
        const float* fb = feats + (size_t)b * SEQ_S * NUM_TAGS;
        const int labBase = b * SEQ_S;

        // Prologue rows 1..7 and first full block rows 8..15
        float fpro[7], fA[8], fB[8];
        #pragma unroll
        for (int d = 0; d < 7; d++) fpro[d] = fb[(1 + d) * NUM_TAGS + lane];
        #pragma unroll
        for (int d = 0; d < 8; d++) fA[d] = fb[(8 + d) * NUM_TAGS + lane];

        const float f0 = fb[lane];
        float alpha = __expf(f0 + sT[START_TAG * NUM_TAGS + lane]);
        float logscale = 0.0f;

#define CRF_STEP(P_, EF_)                                                   \
    {                                                                        \
        sAlpha[w][P_][lane] = alpha;                                         \
        __syncwarp();                                                        \
        const ulonglong2* ap_ = (const ulonglong2*)sAlpha[w][P_];            \
        unsigned long long a0, a1, a2, a3;                                   \
        ulonglong2 v0 = ap_[0], v1 = ap_[1], v2 = ap_[2], v3 = ap_[3];       \
        ulonglong2 v4 = ap_[4], v5 = ap_[5], v6 = ap_[6], v7 = ap_[7];       \
        a0 = fma2(v0.x, Epk[0],  0ull);                                      \
        a1 = fma2(v0.y, Epk[1],  0ull);                                      \
        a2 = fma2(v1.x, Epk[2],  0ull);                                      \
        a3 = fma2(v1.y, Epk[3],  0ull);                                      \
        a0 = fma2(v2.x, Epk[4],  a0);                                        \
        a1 = fma2(v2.y, Epk[5],  a1);                                        \
        a2 = fma2(v3.x, Epk[6],  a2);                                        \
        a3 = fma2(v3.y, Epk[7],  a3);                                        \
        a0 = fma2(v4.x, Epk[8],  a0);                                        \
        a1 = fma2(v4.y, Epk[9],  a1);                                        \
        a2 = fma2(v5.x, Epk[10], a2);                                        \
        a3 = fma2(v5.y, Epk[11], a3);                                        \
        a0 = fma2(v6.x, Epk[12], a0);                                        \
        a1 = fma2(v6.y, Epk[13], a1);                                        \
        a2 = fma2(v7.x, Epk[14], a2);                                        \
        a3 = fma2(v7.y, Epk[15], a3);                                        \
        a0 = add2(a0, a1); a2 = add2(a2, a3); a0 = add2(a0, a2);             \
        float lo_, hi_; unpack2(a0, lo_, hi_);                               \
        alpha = (lo_ + hi_) * (EF_);                                         \
    }

        // Prologue steps t = 1..7 (guarded; p = t&1)
        #pragma unroll
        for (int u = 0; u < 7; u++) {
            if (1 + u < len) {
                const float ef_ = __expf(fpro[u]);
                CRF_STEP((1 + u) & 1, ef_);
            }
        }

        int t = 8;
        // Main loop: 8 steps/iter; batched prefetch of next block; renorm per block
        for (; t + 8 <= len; t += 8) {
            #pragma unroll
            for (int u = 0; u < 8; u++) {
                int r = t + 8 + u; r = (r < SEQ_S) ? r : (SEQ_S - 1);
                fB[u] = fb[r * NUM_TAGS + lane];
            }
            float ef[8];
            #pragma unroll
            for (int u = 0; u < 8; u++) ef[u] = __expf(fA[u]);
            #pragma unroll
            for (int u = 0; u < 8; u++) {
                CRF_STEP(u & 1, ef[u]);
            }
            // Exact power-of-two renormalization via REDUX (alpha >= 0)
            unsigned mb = __reduce_max_sync(0xffffffffu, __float_as_uint(alpha));
            int e = (int)((mb >> 23) & 0xff);
            if (e > 0) {
                int sc = 254 - e; sc = (sc < 1) ? 1 : sc;
                alpha *= __int_as_float(sc << 23);
                logscale += (float)(e - 127) * LN2F;
            }
            #pragma unroll
            for (int u = 0; u < 8; u++) fA[u] = fB[u];
        }
        // Tail: rows t..len-1 are in fA
        #pragma unroll
        for (int u = 0; u < 7; u++) {
            if (t + u < len) {
                const float ef_ = __expf(fA[u]);
                CRF_STEP((t + u) & 1, ef_);
            }
        }
#undef CRF_STEP

        // Gold score epilogue: emit + pair sums, order-independent gather
        float epacc = 0.0f;
        for (int base = 0; base < len; base += 32) {
            const int pos = base + lane;
            const bool v = pos < len;
            const int cp = v ? pos : (len - 1);
            const int lab = labels[labBase + cp];
            const float fv = fb[cp * NUM_TAGS + lab];
            float contrib = fv;
            if (pos >= 1) {
                const int lp = labels[labBase + cp - 1];
                contrib += sT[lp * NUM_TAGS + lab];
            }
            if (v) epacc += contrib;
        }

        float total = alpha;
        #pragma unroll
        for (int off = 16; off >= 1; off >>= 1) {
            total += __shfl_xor_sync(0xffffffffu, total, off);
            epacc += __shfl_xor_sync(0xffffffffu, epacc, off);
        }
        const float fwd = __logf(total) + logscale;

        const int lab0 = labels[labBase];
        const int labL = labels[labBase + len - 1];
        const float gold = epacc + sT[START_TAG * NUM_TAGS + lab0]
                                 + sT[labL * NUM_TAGS + STOP_TAG];

        if (lane == 0) g_partial[b] = fwd - gold;
    }

    // Fused final reduction: last block to finish sums all partials.
    __syncthreads();
    if (tid == 0) {
        __threadfence();
        unsigned r = atomicAdd(&g_done, 1u);
        sIsLast = (r == (unsigned)(nblocks - 1));
    }
    __syncthreads();
    if (sIsLast) {
        __threadfence();
        float s = 0.0f;
        for (int i = tid; i < B; i += 64) s += g_partial[i];
        sred[tid] = s;
        __syncthreads();
        if (tid < 32) {
            float v2 = sred[tid] + sred[tid + 32];
            #pragma unroll
            for (int off = 16; off >= 1; off >>= 1)
                v2 += __shfl_xor_sync(0xffffffffu, v2, off);
            if (tid == 0) {
                out[0] = v2 / (float)B;
                g_done = 0;   // reset for next graph replay
            }
        }
    }
}

extern "C" void kernel_launch(void* const* d_in, const int* in_sizes, int n_in,
                              void* d_out, int out_size)
{
    const float* feats       = (const float*)d_in[0];
    const int*   labels      = (const int*)d_in[1];
    const int*   lengths     = (const int*)d_in[2];
    const float* transitions = (const float*)d_in[3];
    float* out = (float*)d_out;

    const int B = in_sizes[2];
    const int blocks = (B + 1) / 2;

    crf_forward_kernel<<<blocks, 64>>>(feats, labels, lengths, transitions,
                                       out, B, blocks);
}

// round 4
// speedup vs baseline: 2.1743x; 1.1376x over previous
#include <cuda_runtime.h>
#include <cuda_bf16.h>
#include <cstdint>

#define NUM_TAGS 32
#define START_TAG 30
#define STOP_TAG 31
#define MAX_B 1024
#define SEQ_S 512
#define LN2F 0.6931471805599453f

__device__ float g_partial[MAX_B];
__device__ unsigned g_done = 0;

__device__ __forceinline__ unsigned long long fma2(unsigned long long a,
                                                   unsigned long long b,
                                                   unsigned long long c) {
    unsigned long long d;
    asm("fma.rn.f32x2 %0, %1, %2, %3;" : "=l"(d) : "l"(a), "l"(b), "l"(c));
    return d;
}
__device__ __forceinline__ unsigned long long mul2(unsigned long long a,
                                                   unsigned long long b) {
    unsigned long long d;
    asm("mul.rn.f32x2 %0, %1, %2;" : "=l"(d) : "l"(a), "l"(b));
    return d;
}
__device__ __forceinline__ unsigned long long add2(unsigned long long a,
                                                   unsigned long long b) {
    unsigned long long d;
    asm("add.rn.f32x2 %0, %1, %2;" : "=l"(d) : "l"(a), "l"(b));
    return d;
}
__device__ __forceinline__ void unpack2(unsigned long long v, float& lo, float& hi) {
    asm("mov.b64 {%0, %1}, %2;" : "=f"(lo), "=f"(hi) : "l"(v));
}
__device__ __forceinline__ unsigned long long pack2(float lo, float hi) {
    unsigned long long v;
    asm("mov.b64 %0, {%1, %2};" : "=l"(v) : "f"(lo), "f"(hi));
    return v;
}
// Ordered same-warp smem ops: store pins compiler order via memory clobber;
// LSU processes same-warp smem accesses in issue order. Loop body is fully
// convergent (no divergent branches), so no warp-level sync is required.
__device__ __forceinline__ void sts32(uint32_t addr, float v) {
    asm volatile("st.shared.b32 [%0], %1;" :: "r"(addr), "f"(v) : "memory");
}
__device__ __forceinline__ ulonglong2 lds128(uint32_t addr) {
    ulonglong2 r;
    asm volatile("ld.shared.v2.b64 {%0, %1}, [%2];"
                 : "=l"(r.x), "=l"(r.y) : "r"(addr));
    return r;
}

// One warp per batch; lane j owns tag j. Linear-space recursion, branchless
// masked steps, sync-free smem broadcast, stale-feedback renormalization.
__global__ __launch_bounds__(64) void crf_forward_kernel(
    const float* __restrict__ feats,       // [B, 512, 32]
    const int*   __restrict__ labels,      // [B, 512]
    const int*   __restrict__ lengths,     // [B]
    const float* __restrict__ transitions, // [32, 32]
    float* __restrict__ out, int B, int nblocks)
{
    __shared__ float sT[NUM_TAGS * NUM_TAGS];
    __shared__ float sAlpha[2][2][NUM_TAGS];   // [warp][parity][tag]
    __shared__ float sred[64];
    __shared__ int sIsLast;

    const int tid  = threadIdx.x;
    const int w    = tid >> 5;
    const int lane = tid & 31;

    #pragma unroll
    for (int k = 0; k < 16; k++)
        sT[tid + k * 64] = transitions[tid + k * 64];
    __syncthreads();

    const int b = blockIdx.x * 2 + w;

    if (b < B) {
        // Packed E columns: Epk[q] = ( exp(T[2q][lane]), exp(T[2q+1][lane]) )
        unsigned long long Epk[16];
        #pragma unroll
        for (int q = 0; q < 16; q++) {
            float e0 = __expf(sT[(2 * q) * NUM_TAGS + lane]);
            float e1 = __expf(sT[(2 * q + 1) * NUM_TAGS + lane]);
            Epk[q] = pack2(e0, e1);
        }

        const int len = lengths[b];
        const float* fb = feats + (size_t)b * SEQ_S * NUM_TAGS;
        const int labBase = b * SEQ_S;

        const uint32_t a0 = (uint32_t)__cvta_generic_to_shared(&sAlpha[w][0][0]);
        const uint32_t a1 = (uint32_t)__cvta_generic_to_shared(&sAlpha[w][1][0]);
        const uint32_t wr0 = a0 + lane * 4;
        const uint32_t wr1 = a1 + lane * 4;

        // Upfront loads: rows 1..15 (prologue) and rows 16..31 (first block)
        float fpre[15], fA[16], fB[16];
        #pragma unroll
        for (int d = 0; d < 15; d++) fpre[d] = fb[(1 + d) * NUM_TAGS + lane];
        #pragma unroll
        for (int d = 0; d < 16; d++) fA[d] = fb[(16 + d) * NUM_TAGS + lane];

        const float f0 = fb[lane];
        float alpha = __expf(f0 + sT[START_TAG * NUM_TAGS + lane]);
        int ilog = 0;
        unsigned prev_mb = 127u << 23;   // "no scale" seed

#define CRF_STEP(WRA, RDA, EF, VALID)                                        \
    {                                                                         \
        sts32((WRA), alpha);                                                  \
        ulonglong2 q0 = lds128((RDA));       ulonglong2 q1 = lds128((RDA)+16);\
        ulonglong2 q2 = lds128((RDA)+32);    ulonglong2 q3 = lds128((RDA)+48);\
        ulonglong2 q4 = lds128((RDA)+64);    ulonglong2 q5 = lds128((RDA)+80);\
        ulonglong2 q6 = lds128((RDA)+96);    ulonglong2 q7 = lds128((RDA)+112);\
        unsigned long long c0 = mul2(q0.x, Epk[0]);                           \
        unsigned long long c1 = mul2(q0.y, Epk[1]);                           \
        unsigned long long c2 = mul2(q1.x, Epk[2]);                           \
        unsigned long long c3 = mul2(q1.y, Epk[3]);                           \
        unsigned long long c4 = mul2(q2.x, Epk[4]);                           \
        unsigned long long c5 = mul2(q2.y, Epk[5]);                           \
        unsigned long long c6 = mul2(q3.x, Epk[6]);                           \
        unsigned long long c7 = mul2(q3.y, Epk[7]);                           \
        c0 = fma2(q4.x, Epk[8],  c0);                                         \
        c1 = fma2(q4.y, Epk[9],  c1);                                         \
        c2 = fma2(q5.x, Epk[10], c2);                                         \
        c3 = fma2(q5.y, Epk[11], c3);                                         \
        c4 = fma2(q6.x, Epk[12], c4);                                         \
        c5 = fma2(q6.y, Epk[13], c5);                                         \
        c6 = fma2(q7.x, Epk[14], c6);                                         \
        c7 = fma2(q7.y, Epk[15], c7);                                         \
        c0 = add2(c0, c1); c2 = add2(c2, c3);                                 \
        c4 = add2(c4, c5); c6 = add2(c6, c7);                                 \
        c0 = add2(c0, c2); c4 = add2(c4, c6);                                 \
        c0 = add2(c0, c4);                                                    \
        float lo_, hi_; unpack2(c0, lo_, hi_);                                \
        const float an_ = (lo_ + hi_) * (EF);                                 \
        alpha = (VALID) ? an_ : alpha;                                        \
    }

        // Branchless renorm with stale feedback: apply scale derived from the
        // previous group's REDUX, then measure (latency overlaps next group).
#define CRF_RENORM                                                            \
    {                                                                         \
        int e_ = (int)((prev_mb >> 23) & 0xff);                               \
        int sc_ = 254 - e_; sc_ = (sc_ < 1) ? 1 : sc_;                        \
        sc_ = (sc_ > 254) ? 254 : sc_;                                        \
        alpha *= __int_as_float(sc_ << 23);                                   \
        ilog += 127 - sc_;                                                    \
        prev_mb = __reduce_max_sync(0xffffffffu, __float_as_uint(alpha));     \
    }

        // Prologue: masked steps t = 1..15
        #pragma unroll
        for (int u = 0; u < 15; u++) {
            const int t_ = 1 + u;
            const float ef_ = __expf(fpre[u]);
            const uint32_t wrad = (t_ & 1) ? wr1 : wr0;
            const uint32_t rdad = (t_ & 1) ? a1 : a0;
            CRF_STEP(wrad, rdad, ef_, t_ < len);
            if (u == 7) CRF_RENORM;
        }
        CRF_RENORM;

        // Main loop: 16 masked steps per iteration, prefetch 16 rows ahead
        int t = 16;
        while (t < len) {
            #pragma unroll
            for (int u = 0; u < 16; u++) {
                int r = t + 16 + u; r = (r < SEQ_S) ? r : (SEQ_S - 1);
                fB[u] = fb[r * NUM_TAGS + lane];
            }
            float ef[16];
            #pragma unroll
            for (int u = 0; u < 16; u++) ef[u] = __expf(fA[u]);
            #pragma unroll
            for (int u = 0; u < 16; u++) {
                const int t_ = t + u;
                const uint32_t wrad = (t_ & 1) ? wr1 : wr0;
                const uint32_t rdad = (t_ & 1) ? a1 : a0;
                CRF_STEP(wrad, rdad, ef[u], t_ < len);
                if (u == 7) CRF_RENORM;
            }
            CRF_RENORM;
            #pragma unroll
            for (int u = 0; u < 16; u++) fA[u] = fB[u];
            t += 16;
        }
#undef CRF_STEP
#undef CRF_RENORM

        // Gold score epilogue (order-independent, latency tolerant)
        float epacc = 0.0f;
        for (int base = 0; base < len; base += 32) {
            const int pos = base + lane;
            const bool v = pos < len;
            const int cp = v ? pos : (len - 1);
            const int lab = labels[labBase + cp];
            const float fv = fb[cp * NUM_TAGS + lab];
            float contrib = fv;
            if (pos >= 1) {
                const int lp = labels[labBase + cp - 1];
                contrib += sT[lp * NUM_TAGS + lab];
            }
            if (v) epacc += contrib;
        }

        float total = alpha;
        #pragma unroll
        for (int off = 16; off >= 1; off >>= 1) {
            total += __shfl_xor_sync(0xffffffffu, total, off);
            epacc += __shfl_xor_sync(0xffffffffu, epacc, off);
        }
        const float fwd = __logf(total) + (float)ilog * LN2F;

        const int lab0 = labels[labBase];
        const int labL = labels[labBase + len - 1];
        const float gold = epacc + sT[START_TAG * NUM_TAGS + lab0]
                                 + sT[labL * NUM_TAGS + STOP_TAG];

        if (lane == 0) g_partial[b] = fwd - gold;
    }

    // Fused final reduction: last block to finish sums all partials.
    __syncthreads();
    if (tid == 0) {
        __threadfence();
        unsigned r = atomicAdd(&g_done, 1u);
        sIsLast = (r == (unsigned)(nblocks - 1));
    }
    __syncthreads();
    if (sIsLast) {
        __threadfence();
        float s = 0.0f;
        for (int i = tid; i < B; i += 64) s += g_partial[i];
        sred[tid] = s;
        __syncthreads();
        if (tid < 32) {
            float v2 = sred[tid] + sred[tid + 32];
            #pragma unroll
            for (int off = 16; off >= 1; off >>= 1)
                v2 += __shfl_xor_sync(0xffffffffu, v2, off);
            if (tid == 0) {
                out[0] = v2 / (float)B;
                g_done = 0;   // reset for next graph replay
            }
        }
    }
}

extern "C" void kernel_launch(void* const* d_in, const int* in_sizes, int n_in,
                              void* d_out, int out_size)
{
    const float* feats       = (const float*)d_in[0];
    const int*   labels      = (const int*)d_in[1];
    const int*   lengths     = (const int*)d_in[2];
    const float* transitions = (const float*)d_in[3];
    float* out = (float*)d_out;

    const int B = in_sizes[2];
    const int blocks = (B + 1) / 2;

    crf_forward_kernel<<<blocks, 64>>>(feats, labels, lengths, transitions,
                                       out, B, blocks);
}